// round 8
// baseline (speedup 1.0000x reference)
#include <cuda_runtime.h>
#include <cstdint>

// Chamfer distance: ONE persistent kernel, 512 co-resident CTAs (grid barrier
// safe: launch_bounds(256,4) => >=592-CTA capacity), 131072 threads =
// 4 lanes per (cloud,point) query. Fixed box [-4.8,4.8]^3, G=48 (cs=0.2).
// Phases: hist+stage -> CSR scan (1 cell/thread over 110592 cells) ->
// offsets+starts+cursor(+re-zero counts for replay) -> scatter -> 4-lane
// cooperative ring-search query (GROUP-MASK shuffles: loop trip count is
// per-group, full-warp-mask shuffles there deadlock) -> fixed-point u64 sum.

#define NPTS   16384
#define G      48
#define NC     (G * G * G)                 // 110592
#define NCTA   512
#define NTHR   256
#define NTOT   (NCTA * NTHR)               // 131072 = 4 * 2 * NPTS
#define BOXB   4.8f
#define CS     (2.0f * BOXB / (float)G)    // 0.2
#define INV_CS (1.0f / CS)

typedef unsigned long long u64;

// ---------- scratch (__device__ globals; zero-initialized at load) ----------
__device__ int    g_counts[2][NC];         // re-zeroed each run for next replay
__device__ int    g_starts[2][NC + 1];
__device__ int    g_cursor[2][NC];
__device__ int    g_part[2][NCTA];
__device__ float4 g_pre[2][NPTS];          // staged {-2x,-2y,-2z,|p|^2}
__device__ int    g_cellid[2][NPTS];
__device__ float4 g_sorted[2][NPTS];
__device__ u64    g_sum;
__device__ int    g_bar_cnt;
__device__ int    g_bar_sense;

// ---------- device-wide barrier ----------
__device__ __forceinline__ int ld_acq(const int* p) {
    int v; asm volatile("ld.acquire.gpu.b32 %0, [%1];" : "=r"(v) : "l"(p)); return v;
}
__device__ __forceinline__ void st_rel(int* p, int v) {
    asm volatile("st.release.gpu.b32 [%0], %1;" :: "l"(p), "r"(v) : "memory");
}
__device__ __forceinline__ void grid_bar(int& sense) {
    __syncthreads();
    if (threadIdx.x == 0) {
        int target = sense ^ 1;
        __threadfence();
        int a = atomicAdd(&g_bar_cnt, 1);
        if (a == NCTA - 1) {
            atomicExch(&g_bar_cnt, 0);      // reset BEFORE release
            st_rel(&g_bar_sense, target);
        } else {
            while (ld_acq(&g_bar_sense) != target) __nanosleep(32);
        }
        __threadfence();
    }
    sense ^= 1;
    __syncthreads();
}

__device__ __forceinline__ int cell1(float v) {
    int c = (int)floorf((v + BOXB) * INV_CS);
    return c < 0 ? 0 : (c > G - 1 ? G - 1 : c);
}

__device__ __forceinline__ void scan_range(const float4* __restrict__ tgt,
                                           int j, int e,
                                           float qx, float qy, float qz, float& m) {
    for (; j < e; j++) {
        float4 B = __ldg(&tgt[j]);
        float d = fmaf(qz, B.z, fmaf(qy, B.y, fmaf(qx, B.x, B.w)));
        m = fminf(m, d);
    }
}

__global__ __launch_bounds__(NTHR, 4)
void cd_fused_kernel(const float* __restrict__ gt, const float* __restrict__ gen,
                     float* __restrict__ out) {
    __shared__ int sc[NTHR];
    __shared__ int s_off[2];

    const int tid = threadIdx.x;
    const int t   = blockIdx.x * NTHR + tid;        // 0 .. NTOT-1
    int sense = ld_acq(&g_bar_sense);

    // ---- P1: histogram + stage (first 2*NPTS threads, one point each) ----
    if (t < 2 * NPTS) {
        const int cloud = t >> 14, i = t & (NPTS - 1);
        const float* p = (cloud == 0 ? gt : gen) + 3 * i;
        float x = p[0], y = p[1], z = p[2];
        int cell = (cell1(z) * G + cell1(y)) * G + cell1(x);
        atomicAdd(&g_counts[cloud][cell], 1);
        g_pre[cloud][i]    = make_float4(-2.0f * x, -2.0f * y, -2.0f * z,
                                         x * x + y * y + z * z);
        g_cellid[cloud][i] = cell;
    }
    grid_bar(sense);                                // GB1

    // ---- P2a: CTA-local scan, one cell per thread (cidx < NC active) ----
    const int cidx = t;
    const bool cact = (cidx < NC);
    int excl[2];
#pragma unroll
    for (int c = 0; c < 2; c++) {
        int cnt = cact ? g_counts[c][cidx] : 0;
        sc[tid] = cnt;
        __syncthreads();
        for (int st = 1; st < NTHR; st <<= 1) {
            int v = (tid >= st) ? sc[tid - st] : 0;
            __syncthreads();
            sc[tid] += v;
            __syncthreads();
        }
        excl[c] = sc[tid] - cnt;
        if (tid == NTHR - 1) g_part[c][blockIdx.x] = sc[tid];
        __syncthreads();
    }
    grid_bar(sense);                                // GB2

    // ---- P2b: global offsets (sum of parts < my CTA), publish CSR ----
    if (tid < 32) {
#pragma unroll
        for (int c = 0; c < 2; c++) {
            int acc = 0;
#pragma unroll
            for (int k = 0; k < NCTA / 32; k++) {
                int idx = k * 32 + tid;
                int pv = g_part[c][idx];
                if (idx < blockIdx.x) acc += pv;
            }
#pragma unroll
            for (int s = 16; s > 0; s >>= 1)
                acc += __shfl_xor_sync(0xFFFFFFFFu, acc, s);
            if (tid == 0) s_off[c] = acc;
        }
    }
    __syncthreads();
    if (cact) {
#pragma unroll
        for (int c = 0; c < 2; c++) {
            int s = s_off[c] + excl[c];
            g_starts[c][cidx] = s;
            g_cursor[c][cidx] = s;
            g_counts[c][cidx] = 0;                  // re-zero for next replay
        }
    }
    if (t == 0) { g_starts[0][NC] = NPTS; g_starts[1][NC] = NPTS; }
    grid_bar(sense);                                // GB3

    // ---- P3: scatter (first 2*NPTS threads) ----
    if (t < 2 * NPTS) {
        const int cloud = t >> 14, i = t & (NPTS - 1);
        int cell = g_cellid[cloud][i];
        int pos  = atomicAdd(&g_cursor[cloud][cell], 1);
        g_sorted[cloud][pos] = g_pre[cloud][i];
    }
    grid_bar(sense);                                // GB4

    // ---- P4: 4-lane cooperative ring-search query ----
    // All cross-lane ops here use the 4-lane GROUP mask: trip counts differ
    // between groups of the same warp, so full-warp-mask sync ops would hang.
    const unsigned gmask = 0xFu << ((tid & 31) & ~3);
    u64 acc = 0ull;
    {
        const int lane4 = t & 3;
        const int qi    = t >> 2;                   // 0 .. 2*NPTS-1
        const int dir   = qi >> 14;
        const int i     = qi & (NPTS - 1);
        const float4* __restrict__ tgt = g_sorted[dir ^ 1];
        const int*    __restrict__ st  = g_starts[dir ^ 1];

        float4 A = g_sorted[dir][i];                // same for all 4 lanes
        float qx = -0.5f * A.x, qy = -0.5f * A.y, qz = -0.5f * A.z;
        float an = A.w;
        int cx = cell1(qx), cy = cell1(qy), cz = cell1(qz);

        float m = 3.4e38f;
        // r = 1 cube: 9 (dz,dy) rows strided over 4 lanes
        {
            int x0 = max(cx - 1, 0), x1 = min(cx + 1, G - 1);
            for (int k = lane4; k < 9; k += 4) {
                int z = cz + k / 3 - 1, y = cy + k % 3 - 1;
                if ((unsigned)z >= G || (unsigned)y >= G) continue;
                int rb = (z * G + y) * G;
                scan_range(tgt, st[rb + x0], st[rb + x1 + 1], qx, qy, qz, m);
            }
        }
        m = fminf(m, __shfl_xor_sync(gmask, m, 1));
        m = fminf(m, __shfl_xor_sync(gmask, m, 2));

        int r = 1;
        while (r < G) {                             // expand until certified
            float bound = (float)r * CS;
            if (m + an <= bound * bound) break;     // group-uniform after reduce
            r++;
            int side = 2 * r + 1, nrows = side * side;
            int x0 = max(cx - r, 0), x1 = min(cx + r, G - 1);
            for (int k = lane4; k < nrows; k += 4) {
                int dz = k / side - r, dy = k % side - r;
                int z = cz + dz, y = cy + dy;
                if ((unsigned)z >= G || (unsigned)y >= G) continue;
                int rb = (z * G + y) * G;
                if (max(abs(dz), abs(dy)) == r) {
                    scan_range(tgt, st[rb + x0], st[rb + x1 + 1], qx, qy, qz, m);
                } else {
                    if (cx - r >= 0)
                        scan_range(tgt, st[rb + cx - r], st[rb + cx - r + 1], qx, qy, qz, m);
                    if (cx + r <= G - 1)
                        scan_range(tgt, st[rb + cx + r], st[rb + cx + r + 1], qx, qy, qz, m);
                }
            }
            m = fminf(m, __shfl_xor_sync(gmask, m, 1));
            m = fminf(m, __shfl_xor_sync(gmask, m, 2));
        }
        if (lane4 == 0) {
            float d = fmaxf(m + an, 0.0f);
            acc = (u64)((double)d * 4294967296.0);  // x 2^32 fixed point
        }
    }
    __syncwarp();                                   // re-converge full warp
    // warp reduce + one RED per warp (integer => deterministic)
#pragma unroll
    for (int s = 16; s > 0; s >>= 1)
        acc += __shfl_down_sync(0xFFFFFFFFu, acc, s);
    if ((tid & 31) == 0 && acc) atomicAdd(&g_sum, acc);
    grid_bar(sense);                                // GB5

    // ---- P5: finalize + reset accumulator for next replay ----
    if (t == 0) {
        double s = (double)g_sum * (1.0 / 4294967296.0);
        out[0] = (float)(s / (double)NPTS);         // mean1 + mean2
        g_sum = 0ull;
    }
}

extern "C" void kernel_launch(void* const* d_in, const int* in_sizes, int n_in,
                              void* d_out, int out_size) {
    const float* gt  = (const float*)d_in[0];
    const float* gen = (const float*)d_in[1];
    float* out = (float*)d_out;
    cd_fused_kernel<<<NCTA, NTHR>>>(gt, gen, out);
}

// round 9
// speedup vs baseline: 3.2191x; 3.2191x over previous
#include <cuda_runtime.h>
#include <cstdint>

// Chamfer distance: ONE persistent kernel, 512 co-resident CTAs, 131072
// threads = 4 lanes per (cloud,point) query. Fixed box [-4.8,4.8]^3, G=48
// (cs=0.2). Grid search is CAPPED at r<=2 (straight-line, no expansion loop);
// queries not certified at r=2 (~0.5%) go to a work queue and are brute-forced
// cooperatively (8 warps/query, coalesced) after a barrier. This removes the
// serial shell-expansion straggler that pinned R6-R8 at ~150us.
// Determinism: every per-query min is exact; sums are fixed-point u64.

#define NPTS   16384
#define G      48
#define NC     (G * G * G)                 // 110592
#define NCTA   512
#define NTHR   256
#define NTOT   (NCTA * NTHR)               // 131072 = 4 * 2 * NPTS
#define NWARP  (NTOT / 32)                 // 4096
#define BOXB   4.8f
#define CS     (2.0f * BOXB / (float)G)    // 0.2
#define INV_CS (1.0f / CS)
#define WPQ    8                           // warps per fallback query

typedef unsigned long long u64;
typedef unsigned int u32;

// ---------- scratch (__device__ globals; zero-initialized at load) ----------
__device__ int    g_counts[2][NC];         // re-zeroed each run for next replay
__device__ int    g_starts[2][NC + 1];
__device__ int    g_cursor[2][NC];
__device__ int    g_part[2][NCTA];
__device__ float4 g_pre[2][NPTS];          // staged {-2x,-2y,-2z,|p|^2}
__device__ int    g_cellid[2][NPTS];
__device__ float4 g_sorted[2][NPTS];
__device__ int    g_fb[2 * NPTS];          // fallback query ids
__device__ u32    g_fbmin[2 * NPTS];       // fallback results (uint-float)
__device__ int    g_fb_cnt;                // reset each run
__device__ u64    g_sum;                   // reset each run
__device__ int    g_bar_cnt;
__device__ int    g_bar_sense;

// ---------- device-wide barrier ----------
__device__ __forceinline__ int ld_acq(const int* p) {
    int v; asm volatile("ld.acquire.gpu.b32 %0, [%1];" : "=r"(v) : "l"(p)); return v;
}
__device__ __forceinline__ void st_rel(int* p, int v) {
    asm volatile("st.release.gpu.b32 [%0], %1;" :: "l"(p), "r"(v) : "memory");
}
__device__ __forceinline__ void grid_bar(int& sense) {
    __syncthreads();
    if (threadIdx.x == 0) {
        int target = sense ^ 1;
        __threadfence();
        int a = atomicAdd(&g_bar_cnt, 1);
        if (a == NCTA - 1) {
            atomicExch(&g_bar_cnt, 0);      // reset BEFORE release
            st_rel(&g_bar_sense, target);
        } else {
            while (ld_acq(&g_bar_sense) != target) __nanosleep(32);
        }
        __threadfence();
    }
    sense ^= 1;
    __syncthreads();
}

__device__ __forceinline__ int cell1(float v) {
    int c = (int)floorf((v + BOXB) * INV_CS);
    return c < 0 ? 0 : (c > G - 1 ? G - 1 : c);
}

__device__ __forceinline__ void scan_range(const float4* __restrict__ tgt,
                                           int j, int e,
                                           float qx, float qy, float qz, float& m) {
    for (; j < e; j++) {
        float4 B = __ldg(&tgt[j]);
        float d = fmaf(qz, B.z, fmaf(qy, B.y, fmaf(qx, B.x, B.w)));
        m = fminf(m, d);
    }
}

__global__ __launch_bounds__(NTHR, 4)
void cd_fused_kernel(const float* __restrict__ gt, const float* __restrict__ gen,
                     float* __restrict__ out) {
    __shared__ int sc[NTHR];
    __shared__ int s_off[2];

    const int tid = threadIdx.x;
    const int t   = blockIdx.x * NTHR + tid;        // 0 .. NTOT-1
    int sense = ld_acq(&g_bar_sense);

    // ---- P1: histogram + stage + fbmin reinit (first 2*NPTS threads) ----
    if (t < 2 * NPTS) {
        const int cloud = t >> 14, i = t & (NPTS - 1);
        const float* p = (cloud == 0 ? gt : gen) + 3 * i;
        float x = p[0], y = p[1], z = p[2];
        int cell = (cell1(z) * G + cell1(y)) * G + cell1(x);
        atomicAdd(&g_counts[cloud][cell], 1);
        g_pre[cloud][i]    = make_float4(-2.0f * x, -2.0f * y, -2.0f * z,
                                         x * x + y * y + z * z);
        g_cellid[cloud][i] = cell;
        g_fbmin[t] = 0x7F800000u;                   // +inf
    }
    grid_bar(sense);                                // GB1

    // ---- P2a: CTA-local scan, one cell per thread ----
    const int cidx = t;
    const bool cact = (cidx < NC);
    int excl[2];
#pragma unroll
    for (int c = 0; c < 2; c++) {
        int cnt = cact ? g_counts[c][cidx] : 0;
        sc[tid] = cnt;
        __syncthreads();
        for (int st = 1; st < NTHR; st <<= 1) {
            int v = (tid >= st) ? sc[tid - st] : 0;
            __syncthreads();
            sc[tid] += v;
            __syncthreads();
        }
        excl[c] = sc[tid] - cnt;
        if (tid == NTHR - 1) g_part[c][blockIdx.x] = sc[tid];
        __syncthreads();
    }
    grid_bar(sense);                                // GB2

    // ---- P2b: global offsets, publish CSR, re-zero counts ----
    if (tid < 32) {
#pragma unroll
        for (int c = 0; c < 2; c++) {
            int acc = 0;
#pragma unroll
            for (int k = 0; k < NCTA / 32; k++) {
                int idx = k * 32 + tid;
                int pv = g_part[c][idx];
                if (idx < blockIdx.x) acc += pv;
            }
#pragma unroll
            for (int s = 16; s > 0; s >>= 1)
                acc += __shfl_xor_sync(0xFFFFFFFFu, acc, s);
            if (tid == 0) s_off[c] = acc;
        }
    }
    __syncthreads();
    if (cact) {
#pragma unroll
        for (int c = 0; c < 2; c++) {
            int s = s_off[c] + excl[c];
            g_starts[c][cidx] = s;
            g_cursor[c][cidx] = s;
            g_counts[c][cidx] = 0;
        }
    }
    if (t == 0) { g_starts[0][NC] = NPTS; g_starts[1][NC] = NPTS; }
    grid_bar(sense);                                // GB3

    // ---- P3: scatter ----
    if (t < 2 * NPTS) {
        const int cloud = t >> 14, i = t & (NPTS - 1);
        int cell = g_cellid[cloud][i];
        int pos  = atomicAdd(&g_cursor[cloud][cell], 1);
        g_sorted[cloud][pos] = g_pre[cloud][i];
    }
    grid_bar(sense);                                // GB4

    // ---- P4a: 4-lane query, r<=2 only (group-mask shuffles) ----
    const unsigned gmask = 0xFu << ((tid & 31) & ~3);
    u64 acc = 0ull;
    {
        const int lane4 = t & 3;
        const int qi    = t >> 2;                   // 0 .. 2*NPTS-1
        const int dir   = qi >> 14;
        const int i     = qi & (NPTS - 1);
        const float4* __restrict__ tgt = g_sorted[dir ^ 1];
        const int*    __restrict__ st  = g_starts[dir ^ 1];

        float4 A = g_sorted[dir][i];
        float qx = -0.5f * A.x, qy = -0.5f * A.y, qz = -0.5f * A.z;
        float an = A.w;
        int cx = cell1(qx), cy = cell1(qy), cz = cell1(qz);

        float m = 3.4e38f;
        {   // r = 1 cube: 9 rows over 4 lanes
            int x0 = max(cx - 1, 0), x1 = min(cx + 1, G - 1);
            for (int k = lane4; k < 9; k += 4) {
                int z = cz + k / 3 - 1, y = cy + k % 3 - 1;
                if ((unsigned)z >= G || (unsigned)y >= G) continue;
                int rb = (z * G + y) * G;
                scan_range(tgt, st[rb + x0], st[rb + x1 + 1], qx, qy, qz, m);
            }
        }
        m = fminf(m, __shfl_xor_sync(gmask, m, 1));
        m = fminf(m, __shfl_xor_sync(gmask, m, 2));

        if (m + an > CS * CS) {                     // group-uniform escalation
            // r = 2 ring: 25 rows; outer rows full x-range, inner rows edges
            int x0 = max(cx - 2, 0), x1 = min(cx + 2, G - 1);
            for (int k = lane4; k < 25; k += 4) {
                int dz = k / 5 - 2, dy = k % 5 - 2;
                int z = cz + dz, y = cy + dy;
                if ((unsigned)z >= G || (unsigned)y >= G) continue;
                int rb = (z * G + y) * G;
                if (max(abs(dz), abs(dy)) == 2) {
                    scan_range(tgt, st[rb + x0], st[rb + x1 + 1], qx, qy, qz, m);
                } else {
                    if (cx - 2 >= 0)
                        scan_range(tgt, st[rb + cx - 2], st[rb + cx - 1], qx, qy, qz, m);
                    if (cx + 2 <= G - 1)
                        scan_range(tgt, st[rb + cx + 2], st[rb + cx + 3], qx, qy, qz, m);
                }
            }
            m = fminf(m, __shfl_xor_sync(gmask, m, 1));
            m = fminf(m, __shfl_xor_sync(gmask, m, 2));
        }

        if (m + an <= 4.0f * CS * CS) {             // certified at r<=2
            if (lane4 == 0) {
                float d = fmaxf(m + an, 0.0f);
                acc = (u64)((double)d * 4294967296.0);
            }
        } else if (lane4 == 0) {                    // enqueue for brute force
            int slot = atomicAdd(&g_fb_cnt, 1);
            g_fb[slot] = qi;
        }
    }
    __syncwarp();
#pragma unroll
    for (int s = 16; s > 0; s >>= 1)
        acc += __shfl_down_sync(0xFFFFFFFFu, acc, s);
    if ((tid & 31) == 0 && acc) atomicAdd(&g_sum, acc);
    grid_bar(sense);                                // GB5

    // ---- P4b: cooperative brute force of fallback queries ----
    const int nf = *((volatile int*)&g_fb_cnt);
    {
        const int gwid = t >> 5, lane = tid & 31;
        const int njobs = nf * WPQ;
        for (int job = gwid; job < njobs; job += NWARP) {
            int f = job >> 3, slice = job & (WPQ - 1);
            int qi = g_fb[f];
            int dir = qi >> 14, i = qi & (NPTS - 1);
            float4 A = g_sorted[dir][i];
            float qx = -0.5f * A.x, qy = -0.5f * A.y, qz = -0.5f * A.z;
            float an = A.w;
            const float4* __restrict__ tgt = g_sorted[dir ^ 1];
            float m = 3.4e38f;
            int base = slice * (NPTS / WPQ) + lane;
#pragma unroll 4
            for (int j = 0; j < NPTS / WPQ / 32; j++) {   // 64 coalesced loads
                float4 B = __ldg(&tgt[base + j * 32]);
                float d = fmaf(qz, B.z, fmaf(qy, B.y, fmaf(qx, B.x, B.w)));
                m = fminf(m, d);
            }
#pragma unroll
            for (int s = 16; s > 0; s >>= 1)
                m = fminf(m, __shfl_xor_sync(0xFFFFFFFFu, m, s));
            if (lane == 0)
                atomicMin(&g_fbmin[f], __float_as_uint(fmaxf(m + an, 0.0f)));
        }
    }
    grid_bar(sense);                                // GB6

    // ---- P5: CTA0 folds fallback results, finalizes, resets ----
    if (blockIdx.x == 0) {
        u64 a2 = 0ull;
        for (int f = tid; f < nf; f += NTHR)
            a2 += (u64)((double)__uint_as_float(g_fbmin[f]) * 4294967296.0);
#pragma unroll
        for (int s = 16; s > 0; s >>= 1)
            a2 += __shfl_down_sync(0xFFFFFFFFu, a2, s);
        if ((tid & 31) == 0 && a2) atomicAdd(&g_sum, a2);
        __syncthreads();
        if (tid == 0) {
            double s = (double)g_sum * (1.0 / 4294967296.0);
            out[0] = (float)(s / (double)NPTS);     // mean1 + mean2
            g_sum = 0ull;
            g_fb_cnt = 0;
        }
    }
}

extern "C" void kernel_launch(void* const* d_in, const int* in_sizes, int n_in,
                              void* d_out, int out_size) {
    const float* gt  = (const float*)d_in[0];
    const float* gen = (const float*)d_in[1];
    float* out = (float*)d_out;
    cd_fused_kernel<<<NCTA, NTHR>>>(gt, gen, out);
}

// round 10
// speedup vs baseline: 3.3575x; 1.0430x over previous
#include <cuda_runtime.h>
#include <cstdint>

// Chamfer distance: ONE persistent kernel, 512 co-resident CTAs, 131072
// threads = 4 lanes per (cloud,point) query. Fixed box [-4.8,4.8]^3, G=48
// (cs=0.2). Grid search capped at r<=2; uncertified queries (~0.5%) are
// brute-forced cooperatively (8 warps/query) after a barrier.
// R10: both clouds packed into ONE 16+16-bit histogram/scan (all values
// < 2^16, carry-free), warp-shuffle two-level scan (2 syncthreads), and
// batched CSR starts loads in the bulk r=1 scan.
// Determinism: per-query mins exact; sums fixed-point u64.

#define NPTS   16384
#define G      48
#define NC     (G * G * G)                 // 110592
#define NCTA   512
#define NTHR   256
#define NTOT   (NCTA * NTHR)               // 131072 = 4 * 2 * NPTS
#define NWARP  (NTOT / 32)                 // 4096
#define BOXB   4.8f
#define CS     (2.0f * BOXB / (float)G)    // 0.2
#define INV_CS (1.0f / CS)
#define WPQ    8                           // warps per fallback query

typedef unsigned long long u64;
typedef unsigned int u32;

// ---------- scratch (__device__ globals; zero-initialized at load) ----------
__device__ u32    g_pcnt[NC];              // packed counts: c0 | c1<<16 (re-zeroed)
__device__ int    g_starts[2][NC + 1];
__device__ int    g_cursor[2][NC];
__device__ u32    g_part[NCTA];            // packed CTA partial sums
__device__ float4 g_pre[2][NPTS];          // staged {-2x,-2y,-2z,|p|^2}
__device__ int    g_cellid[2][NPTS];
__device__ float4 g_sorted[2][NPTS];
__device__ int    g_fb[2 * NPTS];          // fallback query ids
__device__ u32    g_fbmin[2 * NPTS];       // fallback results (uint-float)
__device__ int    g_fb_cnt;                // reset each run
__device__ u64    g_sum;                   // reset each run
__device__ int    g_bar_cnt;
__device__ int    g_bar_sense;

// ---------- device-wide barrier ----------
__device__ __forceinline__ int ld_acq(const int* p) {
    int v; asm volatile("ld.acquire.gpu.b32 %0, [%1];" : "=r"(v) : "l"(p)); return v;
}
__device__ __forceinline__ void st_rel(int* p, int v) {
    asm volatile("st.release.gpu.b32 [%0], %1;" :: "l"(p), "r"(v) : "memory");
}
__device__ __forceinline__ void grid_bar(int& sense) {
    __syncthreads();
    if (threadIdx.x == 0) {
        int target = sense ^ 1;
        __threadfence();
        int a = atomicAdd(&g_bar_cnt, 1);
        if (a == NCTA - 1) {
            atomicExch(&g_bar_cnt, 0);      // reset BEFORE release
            st_rel(&g_bar_sense, target);
        } else {
            while (ld_acq(&g_bar_sense) != target) __nanosleep(32);
        }
        __threadfence();
    }
    sense ^= 1;
    __syncthreads();
}

__device__ __forceinline__ int cell1(float v) {
    int c = (int)floorf((v + BOXB) * INV_CS);
    return c < 0 ? 0 : (c > G - 1 ? G - 1 : c);
}

__device__ __forceinline__ void scan_range(const float4* __restrict__ tgt,
                                           int j, int e,
                                           float qx, float qy, float qz, float& m) {
    for (; j < e; j++) {
        float4 B = __ldg(&tgt[j]);
        float d = fmaf(qz, B.z, fmaf(qy, B.y, fmaf(qx, B.x, B.w)));
        m = fminf(m, d);
    }
}

__global__ __launch_bounds__(NTHR, 4)
void cd_fused_kernel(const float* __restrict__ gt, const float* __restrict__ gen,
                     float* __restrict__ out) {
    __shared__ u32 s_wsum[8];              // per-warp packed totals
    __shared__ u32 s_off;                  // packed global CTA offset

    const int tid  = threadIdx.x;
    const int t    = blockIdx.x * NTHR + tid;       // 0 .. NTOT-1
    const int wid  = tid >> 5, lane = tid & 31;
    int sense = ld_acq(&g_bar_sense);

    // ---- P1: packed histogram + stage + fbmin reinit ----
    if (t < 2 * NPTS) {
        const int cloud = t >> 14, i = t & (NPTS - 1);
        const float* p = (cloud == 0 ? gt : gen) + 3 * i;
        float x = p[0], y = p[1], z = p[2];
        int cell = (cell1(z) * G + cell1(y)) * G + cell1(x);
        atomicAdd(&g_pcnt[cell], cloud == 0 ? 1u : 0x10000u);
        g_pre[cloud][i]    = make_float4(-2.0f * x, -2.0f * y, -2.0f * z,
                                         x * x + y * y + z * z);
        g_cellid[cloud][i] = cell;
        g_fbmin[t] = 0x7F800000u;                   // +inf
    }
    grid_bar(sense);                                // GB1

    // ---- P2a: packed two-level warp scan, one cell per thread ----
    const int  cidx = t;
    const bool cact = (cidx < NC);
    const u32  cnt  = cact ? g_pcnt[cidx] : 0u;     // carry-free packed halves
    u32 incl = cnt;
#pragma unroll
    for (int s = 1; s < 32; s <<= 1) {
        u32 n = __shfl_up_sync(0xFFFFFFFFu, incl, s);
        if (lane >= s) incl += n;
    }
    if (lane == 31) s_wsum[wid] = incl;
    __syncthreads();
    if (wid == 0) {
        u32 w = (lane < 8) ? s_wsum[lane] : 0u;
#pragma unroll
        for (int s = 1; s < 8; s <<= 1) {
            u32 n = __shfl_up_sync(0xFFFFFFFFu, w, s);
            if (lane >= s) w += n;
        }
        if (lane < 8) s_wsum[lane] = w;             // inclusive warp prefixes
    }
    __syncthreads();
    const u32 wbase = (wid > 0) ? s_wsum[wid - 1] : 0u;
    const u32 excl  = wbase + incl - cnt;           // packed exclusive prefix
    if (tid == NTHR - 1) g_part[blockIdx.x] = wbase + incl;  // packed CTA total
    grid_bar(sense);                                // GB2

    // ---- P2b: packed global offset (sum of parts < my CTA), publish CSR ----
    if (wid == 0) {
        u32 acc = 0u;
#pragma unroll
        for (int k = 0; k < NCTA / 32; k++) {
            int idx = k * 32 + lane;
            u32 pv = g_part[idx];
            if (idx < blockIdx.x) acc += pv;
        }
#pragma unroll
        for (int s = 16; s > 0; s >>= 1)
            acc += __shfl_xor_sync(0xFFFFFFFFu, acc, s);
        if (lane == 0) s_off = acc;
    }
    __syncthreads();
    if (cact) {
        u32 pk = s_off + excl;                      // packed starts
        int s0 = (int)(pk & 0xFFFFu), s1 = (int)(pk >> 16);
        g_starts[0][cidx] = s0;  g_cursor[0][cidx] = s0;
        g_starts[1][cidx] = s1;  g_cursor[1][cidx] = s1;
        g_pcnt[cidx] = 0u;                          // re-zero for next replay
    }
    if (t == 0) { g_starts[0][NC] = NPTS; g_starts[1][NC] = NPTS; }
    grid_bar(sense);                                // GB3

    // ---- P3: scatter ----
    if (t < 2 * NPTS) {
        const int cloud = t >> 14, i = t & (NPTS - 1);
        int cell = g_cellid[cloud][i];
        int pos  = atomicAdd(&g_cursor[cloud][cell], 1);
        g_sorted[cloud][pos] = g_pre[cloud][i];
    }
    grid_bar(sense);                                // GB4

    // ---- P4a: 4-lane query, r<=2 only (group-mask shuffles) ----
    const unsigned gmask = 0xFu << (lane & ~3);
    u64 acc = 0ull;
    {
        const int lane4 = t & 3;
        const int qi    = t >> 2;                   // 0 .. 2*NPTS-1
        const int dir   = qi >> 14;
        const int i     = qi & (NPTS - 1);
        const float4* __restrict__ tgt = g_sorted[dir ^ 1];
        const int*    __restrict__ st  = g_starts[dir ^ 1];

        float4 A = g_sorted[dir][i];
        float qx = -0.5f * A.x, qy = -0.5f * A.y, qz = -0.5f * A.z;
        float an = A.w;
        int cx = cell1(qx), cy = cell1(qy), cz = cell1(qz);

        float m = 3.4e38f;
        {   // r = 1 cube: 9 rows over 4 lanes; batch the starts loads first
            int x0 = max(cx - 1, 0), x1 = min(cx + 1, G - 1);
            int js[3], es[3], nr = 0;
#pragma unroll
            for (int k0 = 0; k0 < 3; k0++) {
                int k = lane4 + k0 * 4;
                if (k < 9) {
                    int z = cz + k / 3 - 1, y = cy + k % 3 - 1;
                    if ((unsigned)z < G && (unsigned)y < G) {
                        int rb = (z * G + y) * G;
                        js[nr] = __ldg(&st[rb + x0]);   // MLP: issued back-to-back
                        es[nr] = __ldg(&st[rb + x1 + 1]);
                        nr++;
                    }
                }
            }
#pragma unroll
            for (int q = 0; q < 3; q++)
                if (q < nr) scan_range(tgt, js[q], es[q], qx, qy, qz, m);
        }
        m = fminf(m, __shfl_xor_sync(gmask, m, 1));
        m = fminf(m, __shfl_xor_sync(gmask, m, 2));

        if (m + an > CS * CS) {                     // group-uniform escalation
            // r = 2 ring: 25 rows; outer rows full x-range, inner rows edges
            int x0 = max(cx - 2, 0), x1 = min(cx + 2, G - 1);
            for (int k = lane4; k < 25; k += 4) {
                int dz = k / 5 - 2, dy = k % 5 - 2;
                int z = cz + dz, y = cy + dy;
                if ((unsigned)z >= G || (unsigned)y >= G) continue;
                int rb = (z * G + y) * G;
                if (max(abs(dz), abs(dy)) == 2) {
                    scan_range(tgt, st[rb + x0], st[rb + x1 + 1], qx, qy, qz, m);
                } else {
                    if (cx - 2 >= 0)
                        scan_range(tgt, st[rb + cx - 2], st[rb + cx - 1], qx, qy, qz, m);
                    if (cx + 2 <= G - 1)
                        scan_range(tgt, st[rb + cx + 2], st[rb + cx + 3], qx, qy, qz, m);
                }
            }
            m = fminf(m, __shfl_xor_sync(gmask, m, 1));
            m = fminf(m, __shfl_xor_sync(gmask, m, 2));
        }

        if (m + an <= 4.0f * CS * CS) {             // certified at r<=2
            if (lane4 == 0) {
                float d = fmaxf(m + an, 0.0f);
                acc = (u64)((double)d * 4294967296.0);
            }
        } else if (lane4 == 0) {                    // enqueue for brute force
            int slot = atomicAdd(&g_fb_cnt, 1);
            g_fb[slot] = qi;
        }
    }
    __syncwarp();
#pragma unroll
    for (int s = 16; s > 0; s >>= 1)
        acc += __shfl_down_sync(0xFFFFFFFFu, acc, s);
    if (lane == 0 && acc) atomicAdd(&g_sum, acc);
    grid_bar(sense);                                // GB5

    // ---- P4b: cooperative brute force of fallback queries ----
    const int nf = *((volatile int*)&g_fb_cnt);
    {
        const int gwid = t >> 5;
        const int njobs = nf * WPQ;
        for (int job = gwid; job < njobs; job += NWARP) {
            int f = job >> 3, slice = job & (WPQ - 1);
            int qi = g_fb[f];
            int dir = qi >> 14, i = qi & (NPTS - 1);
            float4 A = g_sorted[dir][i];
            float qx = -0.5f * A.x, qy = -0.5f * A.y, qz = -0.5f * A.z;
            float an = A.w;
            const float4* __restrict__ tgt = g_sorted[dir ^ 1];
            float m = 3.4e38f;
            int base = slice * (NPTS / WPQ) + lane;
#pragma unroll 4
            for (int j = 0; j < NPTS / WPQ / 32; j++) {   // 64 coalesced loads
                float4 B = __ldg(&tgt[base + j * 32]);
                float d = fmaf(qz, B.z, fmaf(qy, B.y, fmaf(qx, B.x, B.w)));
                m = fminf(m, d);
            }
#pragma unroll
            for (int s = 16; s > 0; s >>= 1)
                m = fminf(m, __shfl_xor_sync(0xFFFFFFFFu, m, s));
            if (lane == 0)
                atomicMin(&g_fbmin[f], __float_as_uint(fmaxf(m + an, 0.0f)));
        }
    }
    grid_bar(sense);                                // GB6

    // ---- P5: CTA0 folds fallback results, finalizes, resets ----
    if (blockIdx.x == 0) {
        u64 a2 = 0ull;
        for (int f = tid; f < nf; f += NTHR)
            a2 += (u64)((double)__uint_as_float(g_fbmin[f]) * 4294967296.0);
#pragma unroll
        for (int s = 16; s > 0; s >>= 1)
            a2 += __shfl_down_sync(0xFFFFFFFFu, a2, s);
        if (lane == 0 && a2) atomicAdd(&g_sum, a2);
        __syncthreads();
        if (tid == 0) {
            double s = (double)g_sum * (1.0 / 4294967296.0);
            out[0] = (float)(s / (double)NPTS);     // mean1 + mean2
            g_sum = 0ull;
            g_fb_cnt = 0;
        }
    }
}

extern "C" void kernel_launch(void* const* d_in, const int* in_sizes, int n_in,
                              void* d_out, int out_size) {
    const float* gt  = (const float*)d_in[0];
    const float* gen = (const float*)d_in[1];
    float* out = (float*)d_out;
    cd_fused_kernel<<<NCTA, NTHR>>>(gt, gen, out);
}

// round 11
// speedup vs baseline: 3.5084x; 1.0449x over previous
#include <cuda_runtime.h>
#include <cstdint>

// Chamfer distance: ONE persistent kernel, 512 co-resident CTAs, 131072
// threads = 4 lanes per (cloud,point) query. Fixed box [-4.8,4.8]^3, G=48
// (cs=0.2). Grid search capped at r<=2; uncertified queries (~0.5%) are
// brute-forced cooperatively (8 warps/query) after one barrier.
// R11: (1) bulk r=1 scan interleaves a lane's <=3 CSR rows (MLP 3, trip
// count = max not sum); (2) GB6 replaced by a fence-ordered finisher ticket
// (last fallback job folds + finalizes; others exit); (3) fallback unroll 8.
// Determinism: per-query mins exact; sums fixed-point u64.

#define NPTS   16384
#define G      48
#define NC     (G * G * G)                 // 110592
#define NCTA   512
#define NTHR   256
#define NTOT   (NCTA * NTHR)               // 131072 = 4 * 2 * NPTS
#define NWARP  (NTOT / 32)                 // 4096
#define BOXB   4.8f
#define CS     (2.0f * BOXB / (float)G)    // 0.2
#define INV_CS (1.0f / CS)
#define WPQ    8                           // warps per fallback query

typedef unsigned long long u64;
typedef unsigned int u32;

// ---------- scratch (__device__ globals; zero-initialized at load) ----------
__device__ u32    g_pcnt[NC];              // packed counts: c0 | c1<<16 (re-zeroed)
__device__ int    g_starts[2][NC + 1];
__device__ int    g_cursor[2][NC];
__device__ u32    g_part[NCTA];            // packed CTA partial sums
__device__ float4 g_pre[2][NPTS];          // staged {-2x,-2y,-2z,|p|^2}
__device__ int    g_cellid[2][NPTS];
__device__ float4 g_sorted[2][NPTS];
__device__ int    g_fb[2 * NPTS];          // fallback query ids
__device__ u32    g_fbmin[2 * NPTS];       // fallback results (uint-float)
__device__ int    g_fb_cnt;                // reset by finisher
__device__ int    g_fb_done;               // finisher ticket; reset by finisher
__device__ u64    g_sum;                   // reset by finisher
__device__ int    g_bar_cnt;
__device__ int    g_bar_sense;

// ---------- device-wide barrier ----------
__device__ __forceinline__ int ld_acq(const int* p) {
    int v; asm volatile("ld.acquire.gpu.b32 %0, [%1];" : "=r"(v) : "l"(p)); return v;
}
__device__ __forceinline__ void st_rel(int* p, int v) {
    asm volatile("st.release.gpu.b32 [%0], %1;" :: "l"(p), "r"(v) : "memory");
}
__device__ __forceinline__ void grid_bar(int& sense) {
    __syncthreads();
    if (threadIdx.x == 0) {
        int target = sense ^ 1;
        __threadfence();
        int a = atomicAdd(&g_bar_cnt, 1);
        if (a == NCTA - 1) {
            atomicExch(&g_bar_cnt, 0);      // reset BEFORE release
            st_rel(&g_bar_sense, target);
        } else {
            while (ld_acq(&g_bar_sense) != target) __nanosleep(32);
        }
        __threadfence();
    }
    sense ^= 1;
    __syncthreads();
}

__device__ __forceinline__ int cell1(float v) {
    int c = (int)floorf((v + BOXB) * INV_CS);
    return c < 0 ? 0 : (c > G - 1 ? G - 1 : c);
}

__device__ __forceinline__ float pdist(float4 B, float qx, float qy, float qz) {
    return fmaf(qz, B.z, fmaf(qy, B.y, fmaf(qx, B.x, B.w)));
}

__device__ __forceinline__ void scan_range(const float4* __restrict__ tgt,
                                           int j, int e,
                                           float qx, float qy, float qz, float& m) {
    for (; j < e; j++) m = fminf(m, pdist(__ldg(&tgt[j]), qx, qy, qz));
}

__global__ __launch_bounds__(NTHR, 4)
void cd_fused_kernel(const float* __restrict__ gt, const float* __restrict__ gen,
                     float* __restrict__ out) {
    __shared__ u32 s_wsum[8];              // per-warp packed totals
    __shared__ u32 s_off;                  // packed global CTA offset

    const int tid  = threadIdx.x;
    const int t    = blockIdx.x * NTHR + tid;       // 0 .. NTOT-1
    const int wid  = tid >> 5, lane = tid & 31;
    int sense = ld_acq(&g_bar_sense);

    // ---- P1: packed histogram + stage + fbmin reinit ----
    if (t < 2 * NPTS) {
        const int cloud = t >> 14, i = t & (NPTS - 1);
        const float* p = (cloud == 0 ? gt : gen) + 3 * i;
        float x = p[0], y = p[1], z = p[2];
        int cell = (cell1(z) * G + cell1(y)) * G + cell1(x);
        atomicAdd(&g_pcnt[cell], cloud == 0 ? 1u : 0x10000u);
        g_pre[cloud][i]    = make_float4(-2.0f * x, -2.0f * y, -2.0f * z,
                                         x * x + y * y + z * z);
        g_cellid[cloud][i] = cell;
        g_fbmin[t] = 0x7F800000u;                   // +inf
    }
    grid_bar(sense);                                // GB1

    // ---- P2a: packed two-level warp scan, one cell per thread ----
    const int  cidx = t;
    const bool cact = (cidx < NC);
    const u32  cnt  = cact ? g_pcnt[cidx] : 0u;     // carry-free packed halves
    u32 incl = cnt;
#pragma unroll
    for (int s = 1; s < 32; s <<= 1) {
        u32 n = __shfl_up_sync(0xFFFFFFFFu, incl, s);
        if (lane >= s) incl += n;
    }
    if (lane == 31) s_wsum[wid] = incl;
    __syncthreads();
    if (wid == 0) {
        u32 w = (lane < 8) ? s_wsum[lane] : 0u;
#pragma unroll
        for (int s = 1; s < 8; s <<= 1) {
            u32 n = __shfl_up_sync(0xFFFFFFFFu, w, s);
            if (lane >= s) w += n;
        }
        if (lane < 8) s_wsum[lane] = w;             // inclusive warp prefixes
    }
    __syncthreads();
    const u32 wbase = (wid > 0) ? s_wsum[wid - 1] : 0u;
    const u32 excl  = wbase + incl - cnt;           // packed exclusive prefix
    if (tid == NTHR - 1) g_part[blockIdx.x] = wbase + incl;  // packed CTA total
    grid_bar(sense);                                // GB2

    // ---- P2b: packed global offset (sum of parts < my CTA), publish CSR ----
    if (wid == 0) {
        u32 acc = 0u;
#pragma unroll
        for (int k = 0; k < NCTA / 32; k++) {
            int idx = k * 32 + lane;
            u32 pv = g_part[idx];
            if (idx < blockIdx.x) acc += pv;
        }
#pragma unroll
        for (int s = 16; s > 0; s >>= 1)
            acc += __shfl_xor_sync(0xFFFFFFFFu, acc, s);
        if (lane == 0) s_off = acc;
    }
    __syncthreads();
    if (cact) {
        u32 pk = s_off + excl;                      // packed starts
        int s0 = (int)(pk & 0xFFFFu), s1 = (int)(pk >> 16);
        g_starts[0][cidx] = s0;  g_cursor[0][cidx] = s0;
        g_starts[1][cidx] = s1;  g_cursor[1][cidx] = s1;
        g_pcnt[cidx] = 0u;                          // re-zero for next replay
    }
    if (t == 0) { g_starts[0][NC] = NPTS; g_starts[1][NC] = NPTS; }
    grid_bar(sense);                                // GB3

    // ---- P3: scatter ----
    if (t < 2 * NPTS) {
        const int cloud = t >> 14, i = t & (NPTS - 1);
        int cell = g_cellid[cloud][i];
        int pos  = atomicAdd(&g_cursor[cloud][cell], 1);
        g_sorted[cloud][pos] = g_pre[cloud][i];
    }
    grid_bar(sense);                                // GB4

    // ---- P4a: 4-lane query, r<=2 only (group-mask shuffles) ----
    const unsigned gmask = 0xFu << (lane & ~3);
    u64 acc = 0ull;
    {
        const int lane4 = t & 3;
        const int qi    = t >> 2;                   // 0 .. 2*NPTS-1
        const int dir   = qi >> 14;
        const int i     = qi & (NPTS - 1);
        const float4* __restrict__ tgt = g_sorted[dir ^ 1];
        const int*    __restrict__ st  = g_starts[dir ^ 1];

        float4 A = g_sorted[dir][i];
        float qx = -0.5f * A.x, qy = -0.5f * A.y, qz = -0.5f * A.z;
        float an = A.w;
        int cx = cell1(qx), cy = cell1(qy), cz = cell1(qz);

        float m = 3.4e38f;
        {   // r = 1 cube: 9 rows over 4 lanes; this lane's <=3 rows scanned
            // INTERLEAVED (3 independent loads in flight, trip count = max len)
            int x0 = max(cx - 1, 0), x1 = min(cx + 1, G - 1);
            int j0 = 0, e0 = 0, j1 = 0, e1 = 0, j2 = 0, e2 = 0;
#pragma unroll
            for (int k0 = 0; k0 < 3; k0++) {
                int k = lane4 + k0 * 4;
                if (k < 9) {
                    int z = cz + k / 3 - 1, y = cy + k % 3 - 1;
                    if ((unsigned)z < G && (unsigned)y < G) {
                        int rb = (z * G + y) * G;
                        int js = __ldg(&st[rb + x0]);
                        int es = __ldg(&st[rb + x1 + 1]);
                        if (k0 == 0) { j0 = js; e0 = es; }
                        else if (k0 == 1) { j1 = js; e1 = es; }
                        else { j2 = js; e2 = es; }
                    }
                }
            }
            while ((j0 < e0) | (j1 < e1) | (j2 < e2)) {
                float4 B0, B1, B2;
                bool a0 = j0 < e0, a1 = j1 < e1, a2 = j2 < e2;
                if (a0) B0 = __ldg(&tgt[j0]);
                if (a1) B1 = __ldg(&tgt[j1]);
                if (a2) B2 = __ldg(&tgt[j2]);
                if (a0) { m = fminf(m, pdist(B0, qx, qy, qz)); j0++; }
                if (a1) { m = fminf(m, pdist(B1, qx, qy, qz)); j1++; }
                if (a2) { m = fminf(m, pdist(B2, qx, qy, qz)); j2++; }
            }
        }
        m = fminf(m, __shfl_xor_sync(gmask, m, 1));
        m = fminf(m, __shfl_xor_sync(gmask, m, 2));

        if (m + an > CS * CS) {                     // group-uniform escalation
            // r = 2 ring: 25 rows; outer rows full x-range, inner rows edges
            int x0 = max(cx - 2, 0), x1 = min(cx + 2, G - 1);
            for (int k = lane4; k < 25; k += 4) {
                int dz = k / 5 - 2, dy = k % 5 - 2;
                int z = cz + dz, y = cy + dy;
                if ((unsigned)z >= G || (unsigned)y >= G) continue;
                int rb = (z * G + y) * G;
                if (max(abs(dz), abs(dy)) == 2) {
                    scan_range(tgt, st[rb + x0], st[rb + x1 + 1], qx, qy, qz, m);
                } else {
                    if (cx - 2 >= 0)
                        scan_range(tgt, st[rb + cx - 2], st[rb + cx - 1], qx, qy, qz, m);
                    if (cx + 2 <= G - 1)
                        scan_range(tgt, st[rb + cx + 2], st[rb + cx + 3], qx, qy, qz, m);
                }
            }
            m = fminf(m, __shfl_xor_sync(gmask, m, 1));
            m = fminf(m, __shfl_xor_sync(gmask, m, 2));
        }

        if (m + an <= 4.0f * CS * CS) {             // certified at r<=2
            if (lane4 == 0) {
                float d = fmaxf(m + an, 0.0f);
                acc = (u64)((double)d * 4294967296.0);
            }
        } else if (lane4 == 0) {                    // enqueue for brute force
            int slot = atomicAdd(&g_fb_cnt, 1);
            g_fb[slot] = qi;
        }
    }
    __syncwarp();
#pragma unroll
    for (int s = 16; s > 0; s >>= 1)
        acc += __shfl_down_sync(0xFFFFFFFFu, acc, s);
    if (lane == 0 && acc) atomicAdd(&g_sum, acc);
    grid_bar(sense);                                // GB5 (last barrier)

    // ---- P4b: cooperative brute force; LAST job's warp finalizes ----
    const int nf = *((volatile int*)&g_fb_cnt);
    const int njobs = nf * WPQ;
    if (njobs > 0) {
        const int gwid = t >> 5;
        for (int job = gwid; job < njobs; job += NWARP) {
            int f = job >> 3, slice = job & (WPQ - 1);
            int qi = g_fb[f];
            int dir = qi >> 14, i = qi & (NPTS - 1);
            float4 A = g_sorted[dir][i];
            float qx = -0.5f * A.x, qy = -0.5f * A.y, qz = -0.5f * A.z;
            float an = A.w;
            const float4* __restrict__ tgt = g_sorted[dir ^ 1];
            float m = 3.4e38f;
            int base = slice * (NPTS / WPQ) + lane;
#pragma unroll 8
            for (int j = 0; j < NPTS / WPQ / 32; j++) {   // 64 coalesced loads
                float4 B = __ldg(&tgt[base + j * 32]);
                m = fminf(m, pdist(B, qx, qy, qz));
            }
#pragma unroll
            for (int s = 16; s > 0; s >>= 1)
                m = fminf(m, __shfl_xor_sync(0xFFFFFFFFu, m, s));
            int ticket = 0;
            if (lane == 0) {
                atomicMin(&g_fbmin[f], __float_as_uint(fmaxf(m + an, 0.0f)));
                __threadfence();
                ticket = atomicAdd(&g_fb_done, 1) + 1;    // jobs completed
            }
            ticket = __shfl_sync(0xFFFFFFFFu, ticket, 0);
            if (ticket == njobs) {                        // this warp is last
                __threadfence();
                u64 a2 = 0ull;
                for (int f2 = lane; f2 < nf; f2 += 32)
                    a2 += (u64)((double)__uint_as_float(
                              *((volatile u32*)&g_fbmin[f2])) * 4294967296.0);
#pragma unroll
                for (int s = 16; s > 0; s >>= 1)
                    a2 += __shfl_down_sync(0xFFFFFFFFu, a2, s);
                if (lane == 0) {
                    u64 tot = atomicAdd(&g_sum, a2) + a2;
                    double sd = (double)tot * (1.0 / 4294967296.0);
                    out[0] = (float)(sd / (double)NPTS);  // mean1 + mean2
                    g_sum = 0ull; g_fb_cnt = 0; g_fb_done = 0;
                    __threadfence();
                }
            }
        }
    } else if (t == 0) {                            // no fallback: finalize now
        u64 tot = atomicAdd(&g_sum, 0ull);
        double sd = (double)tot * (1.0 / 4294967296.0);
        out[0] = (float)(sd / (double)NPTS);
        g_sum = 0ull; g_fb_cnt = 0; g_fb_done = 0;
        __threadfence();
    }
}

extern "C" void kernel_launch(void* const* d_in, const int* in_sizes, int n_in,
                              void* d_out, int out_size) {
    const float* gt  = (const float*)d_in[0];
    const float* gen = (const float*)d_in[1];
    float* out = (float*)d_out;
    cd_fused_kernel<<<NCTA, NTHR>>>(gt, gen, out);
}